// round 3
// baseline (speedup 1.0000x reference)
#include <cuda_runtime.h>
#include <cuda_bf16.h>

// Problem constants (B,L,D fixed by the dataset; derived ones below)
#define BB 64
#define LL 550
#define DD 768
#define RR 3
#define PP 50
#define LEN_KEEP (LL - RR * PP)   // 400
#define D4 (DD / 4)               // 192 float4 per feature row

// Scratch: kept-position ids per (batch, kept-rank). Static device array (no alloc).
__device__ int g_keep[BB * LEN_KEEP];

// Kernel A: one CTA per batch row. Computes stable ranks of the (modified)
// noise vector by counting, writes mask + ids_restore directly into the output
// buffer, and scatters kept ids into g_keep for the gather kernel.
__global__ __launch_bounds__(576, 2)
void rank_kernel(const float* __restrict__ noise,
                 const int*   __restrict__ indexes,
                 float*       __restrict__ out)
{
    __shared__ unsigned int sh_bits[LL];

    const int b = blockIdx.x;
    const int i = threadIdx.x;

    // The 3 masked block indices for this batch row (values in [0,11))
    const int i0 = indexes[b * RR + 0];
    const int i1 = indexes[b * RR + 1];
    const int i2 = indexes[b * RR + 2];

    unsigned int mybits = 0u;
    if (i < LL) {
        const int blk = i / PP;  // positions are aligned 50-blocks
        float v = (blk == i0 || blk == i1 || blk == i2) ? 2.0f : noise[b * LL + i];
        // noise in [0,1) and 2.0 are all non-negative -> IEEE bit pattern is
        // order-isomorphic to the float value.
        mybits = __float_as_uint(v);
        sh_bits[i] = mybits;
    }
    __syncthreads();

    if (i < LL) {
        // Stable rank: count strictly-smaller keys, ties broken by index.
        int rank = 0;
        #pragma unroll 10
        for (int j = 0; j < LL; j++) {
            const unsigned int bj = sh_bits[j];  // warp-uniform -> LDS broadcast
            rank += (int)((bj < mybits) || ((bj == mybits) && (j < i)));
        }

        const int OFF_MASK = BB * LEN_KEEP * DD;        // 19,660,800
        const int OFF_IDS  = OFF_MASK + BB * LL;        // +35,200

        // mask[b,i] = base[ids_restore[b,i]] = (rank >= len_keep)
        out[OFF_MASK + b * LL + i] = (rank >= LEN_KEEP) ? 1.0f : 0.0f;
        // ids_restore[b,i] = rank(i)  (inverse permutation of argsort)
        out[OFF_IDS  + b * LL + i] = (float)rank;

        // ids_shuffle[rank] = i  for the kept prefix
        if (rank < LEN_KEEP)
            g_keep[b * LEN_KEEP + rank] = i;
    }
}

// Kernel B: full-chip gather copy, one float4 per thread.
// x_masked[b, r, :] = x[b, g_keep[b*400 + r], :]
__global__ __launch_bounds__(256)
void gather_kernel(const float4* __restrict__ x,
                   float4*       __restrict__ out)
{
    const int TOTAL = BB * LEN_KEEP * D4;  // 4,915,200
    int t = blockIdx.x * blockDim.x + threadIdx.x;
    if (t >= TOTAL) return;

    const int PER_B = LEN_KEEP * D4;       // 76,800
    int b   = t / PER_B;
    int rem = t - b * PER_B;
    int row = rem / D4;
    int col = rem - row * D4;

    // 192 float4 per row = 6 full warps per row -> this load is warp-uniform.
    int keep = __ldg(&g_keep[b * LEN_KEEP + row]);

    out[t] = x[(b * LL + keep) * D4 + col];
}

extern "C" void kernel_launch(void* const* d_in, const int* in_sizes, int n_in,
                              void* d_out, int out_size)
{
    const float* x       = (const float*)d_in[0];  // (64, 550, 768) f32
    const float* noise   = (const float*)d_in[1];  // (64, 550) f32
    const int*   indexes = (const int*)  d_in[2];  // (64, 3) i32
    float* out = (float*)d_out;  // [x_masked | mask | ids_restore] as f32

    rank_kernel<<<BB, 576>>>(noise, indexes, out);

    const int TOTAL = BB * LEN_KEEP * D4;
    gather_kernel<<<(TOTAL + 255) / 256, 256>>>((const float4*)x, (float4*)out);
}

// round 4
// speedup vs baseline: 1.2468x; 1.2468x over previous
#include <cuda_runtime.h>
#include <cuda_bf16.h>

// Problem constants
#define BB 64
#define LL 550
#define DD 768
#define RR 3
#define PP 50
#define LEN_KEEP (LL - RR * PP)   // 400
#define D4 (DD / 4)               // 192 float4 per feature row

#define SLICES 4                  // rank CTAs per batch row
#define SLICE_LEN 138             // ceil(550/4)
#define RANK_THREADS 160

#define ROWS_PER_BLK 4            // gather rows per CTA
#define GATHER_THREADS 256
#define F4_PER_BLK (ROWS_PER_BLK * D4)   // 768 = 3 * 256

// Scratch: kept-position ids per (batch, kept-rank). Static device array.
__device__ int g_keep[BB * LEN_KEEP];

// ---------------------------------------------------------------------------
// Kernel A: stable ranks by counting. grid = (SLICES, BB), block = 160.
// Every CTA loads the full (modified) noise row into shared; each thread
// ranks one position from its 138-slice. Writes mask + ids_restore + g_keep.
// ---------------------------------------------------------------------------
__global__ __launch_bounds__(RANK_THREADS)
void rank_kernel(const float* __restrict__ noise,
                 const int*   __restrict__ indexes,
                 float*       __restrict__ out)
{
    __shared__ unsigned int sh_bits[LL];

    const int b   = blockIdx.y;
    const int sl  = blockIdx.x;
    const int tid = threadIdx.x;

    const int i0 = indexes[b * RR + 0];
    const int i1 = indexes[b * RR + 1];
    const int i2 = indexes[b * RR + 2];

    // Cooperative load of the full noise row with the 2.0 override.
    for (int j = tid; j < LL; j += RANK_THREADS) {
        const int blk = j / PP;
        float v = (blk == i0 || blk == i1 || blk == i2) ? 2.0f
                                                        : noise[b * LL + j];
        // all values non-negative -> float bits order-isomorphic to value
        sh_bits[j] = __float_as_uint(v);
    }
    __syncthreads();

    const int i = sl * SLICE_LEN + tid;
    if (tid < SLICE_LEN && i < LL) {
        const unsigned int mybits = sh_bits[i];
        int rank = 0;
        #pragma unroll 10
        for (int j = 0; j < LL; j++) {
            const unsigned int bj = sh_bits[j];   // warp-uniform LDS broadcast
            rank += (int)((bj < mybits) || ((bj == mybits) && (j < i)));
        }

        const int OFF_MASK = BB * LEN_KEEP * DD;   // start of mask section
        const int OFF_IDS  = OFF_MASK + BB * LL;   // start of ids_restore

        out[OFF_MASK + b * LL + i] = (rank >= LEN_KEEP) ? 1.0f : 0.0f;
        out[OFF_IDS  + b * LL + i] = (float)rank;

        if (rank < LEN_KEEP)
            g_keep[b * LEN_KEEP + rank] = i;       // ids_shuffle[rank] = i
    }

    // PDL: allow the dependent gather grid to launch; our global stores above
    // are visible to it after its griddepcontrol.wait.
    asm volatile("griddepcontrol.launch_dependents;");
}

// ---------------------------------------------------------------------------
// Kernel B: gather copy. One block = 4 kept rows = 768 float4.
// g_keep staged in shared (no per-thread dependent index chain); each thread
// moves 3 independent float4 with streaming cache hints.
// ---------------------------------------------------------------------------
__global__ __launch_bounds__(GATHER_THREADS)
void gather_kernel(const float4* __restrict__ x,
                   float4*       __restrict__ out)
{
    __shared__ int s_src[ROWS_PER_BLK];   // float4-element base of each src row

    // Wait until the rank grid's g_keep writes are visible (no-op if PDL
    // was not honored and the launches fully serialized).
    asm volatile("griddepcontrol.wait;" ::: "memory");

    const int tid = threadIdx.x;
    if (tid < ROWS_PER_BLK) {
        const int rowg = blockIdx.x * ROWS_PER_BLK + tid;  // = b*400 + rank
        const int b    = rowg / LEN_KEEP;
        const int keep = g_keep[rowg];
        s_src[tid] = (b * LL + keep) * D4;
    }
    __syncthreads();

    // 3 independent float4 per thread (768 = 3 * 256)
    float4 v[3];
    int dst[3];
    #pragma unroll
    for (int k = 0; k < 3; k++) {
        const int idx = k * GATHER_THREADS + tid;   // 0..767
        const int r   = idx / D4;
        const int col = idx - r * D4;
        v[k]   = __ldcs(&x[s_src[r] + col]);
        dst[k] = blockIdx.x * F4_PER_BLK + idx;
    }
    #pragma unroll
    for (int k = 0; k < 3; k++)
        __stcs(&out[dst[k]], v[k]);
}

// ---------------------------------------------------------------------------
extern "C" void kernel_launch(void* const* d_in, const int* in_sizes, int n_in,
                              void* d_out, int out_size)
{
    const float* x       = (const float*)d_in[0];  // (64, 550, 768) f32
    const float* noise   = (const float*)d_in[1];  // (64, 550) f32
    const int*   indexes = (const int*)  d_in[2];  // (64, 3) i32
    float* out = (float*)d_out;   // [x_masked | mask | ids_restore] as f32

    rank_kernel<<<dim3(SLICES, BB), RANK_THREADS>>>(noise, indexes, out);

    // Gather with programmatic dependent launch: overlaps launch latency with
    // the tail of rank_kernel; correctness guarded by griddepcontrol.wait.
    cudaLaunchConfig_t cfg = {};
    cfg.gridDim  = dim3((BB * LEN_KEEP) / ROWS_PER_BLK);   // 6400
    cfg.blockDim = dim3(GATHER_THREADS);
    cudaLaunchAttribute attr[1];
    attr[0].id = cudaLaunchAttributeProgrammaticStreamSerialization;
    attr[0].val.programmaticStreamSerializationAllowed = 1;
    cfg.attrs    = attr;
    cfg.numAttrs = 1;
    cudaLaunchKernelEx(&cfg, gather_kernel, (const float4*)x, (float4*)out);
}